// round 12
// baseline (speedup 1.0000x reference)
#include <cuda_runtime.h>
#include <math.h>

#define NN 100000
#define EE 1280000
#define DIN 64
#define DOUT 64
#define DEDGE 16
#define NEG 0.01f
#define W1COLS (DIN + DEDGE)

#define SCAN_T 512
#define SCAN_BLOCKS ((NN + SCAN_T - 1) / SCAN_T)   // 196

#define TM 128                                     // nodes per k_node block
#define NODE_BLOCKS ((NN + TM - 1) / TM)           // 782

typedef unsigned long long ull;

// ---------------- device scratch (static, no allocation) ----------------
__device__ float  g_xt[NN * DOUT];      // x @ W2^T, natural [n][d]
__device__ float  g_sf[NN * DOUT];      // x @ W1a^T, natural [n][d]
__device__ float  g_rdot[NN];
__device__ float2 g_ls[EE];             // CSR-ordered {logit, src-as-bits}
__device__ int    g_count[NN];
__device__ int    g_rowptr[NN + 1];
__device__ int    g_wptr[NN];
__device__ int    g_bsum[SCAN_BLOCKS];

__device__ __forceinline__ float leaky(float v) {
    return fmaxf(v, NEG * v);
}
__device__ __forceinline__ float warp_sum(float v) {
    #pragma unroll
    for (int o = 16; o > 0; o >>= 1) v += __shfl_xor_sync(0xFFFFFFFFu, v, o);
    return v;
}
__device__ __forceinline__ float warp_max(float v) {
    #pragma unroll
    for (int o = 16; o > 0; o >>= 1) v = fmaxf(v, __shfl_xor_sync(0xFFFFFFFFu, v, o));
    return v;
}

// packed f32x2 helpers
__device__ __forceinline__ ull packf2(float lo, float hi) {
    ull r;
    asm("mov.b64 %0, {%1, %2};" : "=l"(r) : "f"(lo), "f"(hi));
    return r;
}
__device__ __forceinline__ void unpackf2(ull v, float& lo, float& hi) {
    asm("mov.b64 {%0, %1}, %2;" : "=f"(lo), "=f"(hi) : "l"(v));
}
__device__ __forceinline__ void ffma2(ull& acc, ull a, ull b) {
    asm("fma.rn.f32x2 %0, %1, %2, %0;" : "+l"(acc) : "l"(a), "l"(b));
}

// ---------------- K0: zero histogram ----------------
__global__ void k_zero_counts() {
    int i = blockIdx.x * blockDim.x + threadIdx.x;
    if (i < NN) g_count[i] = 0;
}

// ---------------- Kh: dst histogram (4 edges/thread) ----------------
__global__ __launch_bounds__(256) void k_hist(const int* __restrict__ dst) {
    int t = blockIdx.x * blockDim.x + threadIdx.x;
    if (t * 4 < EE) {
        int4 d4 = ((const int4*)dst)[t];
        atomicAdd(&g_count[d4.x], 1);
        atomicAdd(&g_count[d4.y], 1);
        atomicAdd(&g_count[d4.z], 1);
        atomicAdd(&g_count[d4.w], 1);
    }
}

// ---------------- K1: node precompute (register-tiled GEMM) ----------------
__global__ __launch_bounds__(256, 2) void k_node(const float* __restrict__ x,
                                                 const float* __restrict__ W1,
                                                 const float* __restrict__ W2,
                                                 const float* __restrict__ attn) {
    __shared__ float xS[TM][65];
    __shared__ float sW[DIN][128];        // [k][d]; d<64: W1a, d>=64: W2
    __shared__ float sAttnR[DIN];

    const int tid = threadIdx.x;
    const int n0  = blockIdx.x * TM;

    for (int idx = tid; idx < DIN * 128; idx += 256) {
        int k = idx >> 7, d = idx & 127;
        sW[k][d] = (d < 64) ? W1[d * W1COLS + k]
                            : W2[(d - 64) * DIN + k];
    }
    if (tid < DIN) sAttnR[tid] = attn[DOUT + tid];

    for (int idx = tid; idx < TM * DIN; idx += 256) {
        int nl = idx >> 6, k = idx & 63;
        int n = n0 + nl;
        if (n >= NN) n = NN - 1;
        xS[nl][k] = x[n * DIN + k];
    }
    __syncthreads();

    const int ty = tid >> 4, tx = tid & 15;
    const int nbase = ty * 8;

    ull acc[8][4];
    #pragma unroll
    for (int j = 0; j < 8; j++)
        #pragma unroll
        for (int p = 0; p < 4; p++) acc[j][p] = 0ULL;

    #pragma unroll 4
    for (int k = 0; k < DIN; k++) {
        ulonglong2 wA = *reinterpret_cast<const ulonglong2*>(&sW[k][tx * 8]);
        ulonglong2 wB = *reinterpret_cast<const ulonglong2*>(&sW[k][tx * 8 + 4]);
        #pragma unroll
        for (int j = 0; j < 8; j++) {
            float xv = xS[nbase + j][k];
            ull xp = packf2(xv, xv);
            ffma2(acc[j][0], wA.x, xp);
            ffma2(acc[j][1], wA.y, xp);
            ffma2(acc[j][2], wB.x, xp);
            ffma2(acc[j][3], wB.y, xp);
        }
    }

    if (tid < TM) {
        int n = n0 + tid;
        if (n < NN) {
            float rd = 0.0f;
            #pragma unroll 8
            for (int k = 0; k < DIN; k++)
                rd += leaky(xS[tid][k]) * sAttnR[k];
            g_rdot[n] = rd;
        }
    }

    #pragma unroll
    for (int j = 0; j < 8; j++) {
        int n = n0 + nbase + j;
        if (n >= NN) continue;
        float* dstp = (tx < 8) ? &g_sf[n * DOUT + tx * 8]
                               : &g_xt[n * DOUT + (tx - 8) * 8];
        ulonglong2 v0; v0.x = acc[j][0]; v0.y = acc[j][1];
        ulonglong2 v1; v1.x = acc[j][2]; v1.y = acc[j][3];
        *reinterpret_cast<ulonglong2*>(dstp)     = v0;
        *reinterpret_cast<ulonglong2*>(dstp + 4) = v1;
    }
}

// ---------------- scan counts -> rowptr ----------------
__global__ __launch_bounds__(SCAN_T) void k_scan1() {
    __shared__ int sh[SCAN_T];
    int i = blockIdx.x * SCAN_T + threadIdx.x;
    int v = (i < NN) ? g_count[i] : 0;
    sh[threadIdx.x] = v;
    __syncthreads();
    #pragma unroll
    for (int off = 1; off < SCAN_T; off <<= 1) {
        int t = (threadIdx.x >= off) ? sh[threadIdx.x - off] : 0;
        __syncthreads();
        sh[threadIdx.x] += t;
        __syncthreads();
    }
    if (i < NN) g_rowptr[i] = sh[threadIdx.x] - v;   // exclusive
    if (threadIdx.x == SCAN_T - 1) g_bsum[blockIdx.x] = sh[SCAN_T - 1];
}

__global__ __launch_bounds__(256) void k_scan2() {
    __shared__ int sh[256];
    int t = threadIdx.x;
    int v = (t < SCAN_BLOCKS) ? g_bsum[t] : 0;
    sh[t] = v;
    __syncthreads();
    #pragma unroll
    for (int off = 1; off < 256; off <<= 1) {
        int tv = (t >= off) ? sh[t - off] : 0;
        __syncthreads();
        sh[t] += tv;
        __syncthreads();
    }
    if (t < SCAN_BLOCKS) g_bsum[t] = sh[t] - v;      // exclusive
}

__global__ void k_scan3() {
    int i = blockIdx.x * blockDim.x + threadIdx.x;
    if (i < NN) {
        int r = g_rowptr[i] + g_bsum[i / SCAN_T];
        g_rowptr[i] = r;
        g_wptr[i]   = r;
    }
    if (i == 0) g_rowptr[NN] = EE;
}

// ---------------- K2: per-edge logits, k-paired f32x2 (zero packing) ----------
// Lane L owns dims (2L, 2L+1). Accumulators pair over k: acc = (even-k, odd-k)
// partials for ONE dim. Edge pairs (e[2j],e[2j+1]) come directly from
// ulonglong2 LDG.128 of edge_attr — no mov.b64 packing in the hot loop.
__global__ __launch_bounds__(256) void k_logits(const float* __restrict__ edge_attr,
                                                const int* __restrict__ src,
                                                const int* __restrict__ dst,
                                                const float* __restrict__ W1,
                                                const float* __restrict__ attn) {
    __shared__ float sP[8][32][33];      // [warp][edge][lane], padded

    const int L = threadIdx.x & 31;
    const int w = threadIdx.x >> 5;

    // weight pairs over k: wA[j] = (W1b[2L][2j], W1b[2L][2j+1]), wB for dim 2L+1
    ull wA[8], wB[8];
    #pragma unroll
    for (int j = 0; j < 8; j++) {
        float2 a = *reinterpret_cast<const float2*>(&W1[(2 * L) * W1COLS + DIN + 2 * j]);
        float2 b = *reinterpret_cast<const float2*>(&W1[(2 * L + 1) * W1COLS + DIN + 2 * j]);
        wA[j] = packf2(a.x, a.y);
        wB[j] = packf2(b.x, b.y);
    }
    const float aL = __ldg(&attn[2 * L]);
    const float aH = __ldg(&attn[2 * L + 1]);

    const int gwarp = blockIdx.x * 8 + w;        // 256 edges/block
    const int base  = gwarp * 32;

    const int s_own = src[base + L];             // coalesced
    const int d_own = dst[base + L];             // coalesced
    const ulonglong2* eaU = (const ulonglong2*)edge_attr;   // 16B = 4 k-values

    // Phase A: partials
    #pragma unroll 2
    for (int i = 0; i < 32; i++) {
        const int e = base + i;
        const int s = __shfl_sync(0xFFFFFFFFu, s_own, i);

        float2 sf = *reinterpret_cast<const float2*>(&g_sf[s * DOUT + 2 * L]);

        ull accA = 0ULL, accB = 0ULL;
        ulonglong2 ea0 = __ldg(&eaU[e * 4 + 0]);    // k0..k3 (2 pairs)
        ffma2(accA, ea0.x, wA[0]);  ffma2(accB, ea0.x, wB[0]);
        ffma2(accA, ea0.y, wA[1]);  ffma2(accB, ea0.y, wB[1]);
        ulonglong2 ea1 = __ldg(&eaU[e * 4 + 1]);    // k4..k7
        ffma2(accA, ea1.x, wA[2]);  ffma2(accB, ea1.x, wB[2]);
        ffma2(accA, ea1.y, wA[3]);  ffma2(accB, ea1.y, wB[3]);
        ulonglong2 ea2 = __ldg(&eaU[e * 4 + 2]);    // k8..k11
        ffma2(accA, ea2.x, wA[4]);  ffma2(accB, ea2.x, wB[4]);
        ffma2(accA, ea2.y, wA[5]);  ffma2(accB, ea2.y, wB[5]);
        ulonglong2 ea3 = __ldg(&eaU[e * 4 + 3]);    // k12..k15
        ffma2(accA, ea3.x, wA[6]);  ffma2(accB, ea3.x, wB[6]);
        ffma2(accA, ea3.y, wA[7]);  ffma2(accB, ea3.y, wB[7]);

        float aLo, aHi, bLo, bHi;
        unpackf2(accA, aLo, aHi);
        unpackf2(accB, bLo, bHi);
        float fA = sf.x + aLo + aHi;
        float fB = sf.y + bLo + bHi;
        sP[w][i][L] = leaky(fA) * aL + leaky(fB) * aH;
    }
    __syncwarp();

    // Phase B: lane L reduces its own edge (row L), conflict-free via pad 33
    float s0 = 0.f, s1 = 0.f, s2 = 0.f, s3 = 0.f;
    #pragma unroll
    for (int j = 0; j < 32; j += 4) {
        s0 += sP[w][L][j];
        s1 += sP[w][L][j + 1];
        s2 += sP[w][L][j + 2];
        s3 += sP[w][L][j + 3];
    }
    float logit = (s0 + s1) + (s2 + s3) + g_rdot[d_own];

    int pos = atomicAdd(&g_wptr[d_own], 1);               // spread-address
    g_ls[pos] = make_float2(logit, __int_as_float(s_own));
}

// ---------------- K5: warp-per-dst softmax + aggregation ----------------
__global__ __launch_bounds__(256) void k_aggregate(const float* __restrict__ bias,
                                                   float* __restrict__ out) {
    __shared__ float2 sA[8][32];          // [warp][idx] = {alpha, src-bits}

    const int lane = threadIdx.x & 31;
    const int w    = threadIdx.x >> 5;
    const int gw   = (blockIdx.x * blockDim.x + threadIdx.x) >> 5;
    if (gw >= NN) return;
    const int n = gw;

    int beg = g_rowptr[n];
    int end = g_rowptr[n + 1];
    int cnt = end - beg;

    float b0 = bias[2 * lane];
    float b1 = bias[2 * lane + 1];

    if (cnt == 0) {
        out[n * DOUT + 2 * lane]     = b0;
        out[n * DOUT + 2 * lane + 1] = b1;
        return;
    }

    float2 v = make_float2(-INFINITY, 0.0f);
    if (lane < cnt) v = g_ls[beg + lane];

    float lm = v.x;
    for (int j = beg + 32 + lane; j < end; j += 32)
        lm = fmaxf(lm, g_ls[j].x);
    float m = warp_max(lm);

    float le = (lane < cnt) ? __expf(v.x - m) : 0.0f;
    for (int j = beg + 32 + lane; j < end; j += 32)
        le += __expf(g_ls[j].x - m);
    float inv = 1.0f / warp_sum(le);

    sA[w][lane] = make_float2((lane < cnt) ? __expf(v.x - m) * inv : 0.0f, v.y);
    __syncwarp();

    float acc0 = 0.0f, acc1 = 0.0f;
    int lim = cnt < 32 ? cnt : 32;
    #pragma unroll 4
    for (int idx = 0; idx < lim; idx++) {
        float2 t = sA[w][idx];            // broadcast LDS.64
        int   s = __float_as_int(t.y);
        float a = t.x;
        float2 xv = *reinterpret_cast<const float2*>(&g_xt[s * DOUT + 2 * lane]);
        acc0 = fmaf(a, xv.x, acc0);
        acc1 = fmaf(a, xv.y, acc1);
    }
    for (int j = beg + 32; j < end; j++) {
        float2 lsv = g_ls[j];
        int   s = __float_as_int(lsv.y);
        float a = __expf(lsv.x - m) * inv;
        float2 xv = *reinterpret_cast<const float2*>(&g_xt[s * DOUT + 2 * lane]);
        acc0 = fmaf(a, xv.x, acc0);
        acc1 = fmaf(a, xv.y, acc1);
    }
    out[n * DOUT + 2 * lane]     = acc0 + b0;
    out[n * DOUT + 2 * lane + 1] = acc1 + b1;
}

// ---------------- launch ----------------
extern "C" void kernel_launch(void* const* d_in, const int* in_sizes, int n_in,
                              void* d_out, int out_size) {
    const float* x         = (const float*)d_in[0];
    const float* edge_attr = (const float*)d_in[1];
    const int*   src       = (const int*)d_in[2];
    const int*   dst       = (const int*)d_in[3];
    const float* W1        = (const float*)d_in[4];
    const float* W2        = (const float*)d_in[5];
    const float* attn      = (const float*)d_in[6];
    const float* bias      = (const float*)d_in[7];
    float* out             = (float*)d_out;

    k_zero_counts<<<(NN + 255) / 256, 256>>>();
    k_hist<<<(EE / 4 + 255) / 256, 256>>>(dst);
    k_node<<<NODE_BLOCKS, 256>>>(x, W1, W2, attn);
    k_scan1<<<SCAN_BLOCKS, SCAN_T>>>();
    k_scan2<<<1, 256>>>();
    k_scan3<<<(NN + 255) / 256, 256>>>();
    k_logits<<<EE / 256, 256>>>(edge_attr, src, dst, W1, attn);
    k_aggregate<<<(NN * 32 + 255) / 256, 256>>>(bias, out);
}

// round 13
// speedup vs baseline: 1.3030x; 1.3030x over previous
#include <cuda_runtime.h>
#include <math.h>

#define NN 100000
#define EE 1280000
#define DIN 64
#define DOUT 64
#define DEDGE 16
#define NEG 0.01f

#define SCAN_T 512
#define SCAN_BLOCKS ((NN + SCAN_T - 1) / SCAN_T)   // 196

#define TM 128                                     // nodes per k_node block
#define NODE_BLOCKS ((NN + TM - 1) / TM)           // 782

typedef unsigned long long ull;

// ---------------- device scratch (static, no allocation) ----------------
__device__ float  g_xt[NN * DOUT];      // x @ W2^T, natural [n][d]
__device__ float  g_sf[NN * DOUT];      // x @ W1a^T, natural [n][d]
__device__ float  g_rdot[NN];
__device__ float2 g_ls[EE];             // CSR-ordered {logit, src-as-bits}
__device__ int    g_count[NN];
__device__ int    g_rowptr[NN + 1];
__device__ int    g_wptr[NN];
__device__ int    g_bsum[SCAN_BLOCKS];

__device__ __forceinline__ float leaky(float v) {
    return fmaxf(v, NEG * v);
}
__device__ __forceinline__ float warp_sum(float v) {
    #pragma unroll
    for (int o = 16; o > 0; o >>= 1) v += __shfl_xor_sync(0xFFFFFFFFu, v, o);
    return v;
}
__device__ __forceinline__ float warp_max(float v) {
    #pragma unroll
    for (int o = 16; o > 0; o >>= 1) v = fmaxf(v, __shfl_xor_sync(0xFFFFFFFFu, v, o));
    return v;
}

// packed f32x2 helpers
__device__ __forceinline__ ull packf2(float lo, float hi) {
    ull r;
    asm("mov.b64 %0, {%1, %2};" : "=l"(r) : "f"(lo), "f"(hi));
    return r;
}
__device__ __forceinline__ void unpackf2(ull v, float& lo, float& hi) {
    asm("mov.b64 {%0, %1}, %2;" : "=f"(lo), "=f"(hi) : "l"(v));
}
__device__ __forceinline__ void ffma2(ull& acc, ull a, ull b) {
    asm("fma.rn.f32x2 %0, %1, %2, %0;" : "+l"(acc) : "l"(a), "l"(b));
}

// ---------------- Kh: dst histogram (4 edges/thread) ----------------
__global__ __launch_bounds__(256) void k_hist(const int* __restrict__ dst) {
    int t = blockIdx.x * blockDim.x + threadIdx.x;
    if (t * 4 < EE) {
        int4 d4 = ((const int4*)dst)[t];
        atomicAdd(&g_count[d4.x], 1);
        atomicAdd(&g_count[d4.y], 1);
        atomicAdd(&g_count[d4.z], 1);
        atomicAdd(&g_count[d4.w], 1);
    }
}

// ---------------- K1: node precompute (register-tiled GEMM) ----------------
__global__ __launch_bounds__(256, 2) void k_node(const float* __restrict__ x,
                                                 const float* __restrict__ W1,
                                                 const float* __restrict__ W2,
                                                 const float* __restrict__ attn) {
    __shared__ float xS[TM][65];
    __shared__ float sW[DIN][128];        // [k][d]; d<64: W1a, d>=64: W2
    __shared__ float sAttnR[DIN];

    const int tid = threadIdx.x;
    const int n0  = blockIdx.x * TM;

    for (int idx = tid; idx < DIN * 128; idx += 256) {
        int k = idx >> 7, d = idx & 127;
        sW[k][d] = (d < 64) ? W1[d * (DIN + DEDGE) + k]
                            : W2[(d - 64) * DIN + k];
    }
    if (tid < DIN) sAttnR[tid] = attn[DOUT + tid];

    for (int idx = tid; idx < TM * DIN; idx += 256) {
        int nl = idx >> 6, k = idx & 63;
        int n = n0 + nl;
        if (n >= NN) n = NN - 1;
        xS[nl][k] = x[n * DIN + k];
    }
    __syncthreads();

    const int ty = tid >> 4, tx = tid & 15;
    const int nbase = ty * 8;

    ull acc[8][4];
    #pragma unroll
    for (int j = 0; j < 8; j++)
        #pragma unroll
        for (int p = 0; p < 4; p++) acc[j][p] = 0ULL;

    #pragma unroll 4
    for (int k = 0; k < DIN; k++) {
        ulonglong2 wA = *reinterpret_cast<const ulonglong2*>(&sW[k][tx * 8]);
        ulonglong2 wB = *reinterpret_cast<const ulonglong2*>(&sW[k][tx * 8 + 4]);
        #pragma unroll
        for (int j = 0; j < 8; j++) {
            float xv = xS[nbase + j][k];
            ull xp = packf2(xv, xv);
            ffma2(acc[j][0], wA.x, xp);
            ffma2(acc[j][1], wA.y, xp);
            ffma2(acc[j][2], wB.x, xp);
            ffma2(acc[j][3], wB.y, xp);
        }
    }

    if (tid < TM) {
        int n = n0 + tid;
        if (n < NN) {
            float rd = 0.0f;
            #pragma unroll 8
            for (int k = 0; k < DIN; k++)
                rd += leaky(xS[tid][k]) * sAttnR[k];
            g_rdot[n] = rd;
        }
    }

    #pragma unroll
    for (int j = 0; j < 8; j++) {
        int n = n0 + nbase + j;
        if (n >= NN) continue;
        float* dstp = (tx < 8) ? &g_sf[n * DOUT + tx * 8]
                               : &g_xt[n * DOUT + (tx - 8) * 8];
        ulonglong2 v0; v0.x = acc[j][0]; v0.y = acc[j][1];
        ulonglong2 v1; v1.x = acc[j][2]; v1.y = acc[j][3];
        *reinterpret_cast<ulonglong2*>(dstp)     = v0;
        *reinterpret_cast<ulonglong2*>(dstp + 4) = v1;
    }
}

// ---------------- scan counts -> rowptr ----------------
__global__ __launch_bounds__(SCAN_T) void k_scan1() {
    __shared__ int sh[SCAN_T];
    int i = blockIdx.x * SCAN_T + threadIdx.x;
    int v = (i < NN) ? g_count[i] : 0;
    sh[threadIdx.x] = v;
    __syncthreads();
    #pragma unroll
    for (int off = 1; off < SCAN_T; off <<= 1) {
        int t = (threadIdx.x >= off) ? sh[threadIdx.x - off] : 0;
        __syncthreads();
        sh[threadIdx.x] += t;
        __syncthreads();
    }
    if (i < NN) g_rowptr[i] = sh[threadIdx.x] - v;   // exclusive
    if (threadIdx.x == SCAN_T - 1) g_bsum[blockIdx.x] = sh[SCAN_T - 1];
}

// fused scan of block sums (redundant per block, trivial) + rowptr finalize
__global__ __launch_bounds__(256) void k_scan23() {
    __shared__ int sh[256];
    __shared__ int exs[256];
    int t = threadIdx.x;
    int v = (t < SCAN_BLOCKS) ? g_bsum[t] : 0;
    sh[t] = v;
    __syncthreads();
    #pragma unroll
    for (int off = 1; off < 256; off <<= 1) {
        int tv = (t >= off) ? sh[t - off] : 0;
        __syncthreads();
        sh[t] += tv;
        __syncthreads();
    }
    exs[t] = sh[t] - v;                   // exclusive
    __syncthreads();

    int i = blockIdx.x * 256 + t;
    if (i < NN) {
        int r = g_rowptr[i] + exs[i >> 9];
        g_rowptr[i] = r;
        g_wptr[i]   = r;
    }
    if (i == 0) g_rowptr[NN] = EE;
}

// ---------------- K2: per-edge logits, transpose-reduced, per-lane scatter ----
// R6-proven form, untouched: all 16 weight pairs resident in registers.
__global__ __launch_bounds__(256) void k_logits(const float* __restrict__ edge_attr,
                                                const int* __restrict__ src,
                                                const int* __restrict__ dst,
                                                const float* __restrict__ W1,
                                                const float* __restrict__ attn) {
    __shared__ float2 sW[DEDGE * 32];    // [k][L] = (W1b[2L][k], W1b[2L+1][k])
    __shared__ float  sP[8][32][33];     // [warp][edge][lane], padded

    for (int idx = threadIdx.x; idx < DEDGE * 32; idx += blockDim.x) {
        int k = idx >> 5, L = idx & 31;
        sW[idx] = make_float2(W1[(2 * L) * (DIN + DEDGE) + DIN + k],
                              W1[(2 * L + 1) * (DIN + DEDGE) + DIN + k]);
    }
    __syncthreads();

    const int L = threadIdx.x & 31;
    const int w = threadIdx.x >> 5;

    ull wp[DEDGE];
    #pragma unroll
    for (int k = 0; k < DEDGE; k++) {
        float2 t = sW[k * 32 + L];
        wp[k] = packf2(t.x, t.y);
    }
    const float aL = __ldg(&attn[2 * L]);
    const float aH = __ldg(&attn[2 * L + 1]);

    const int gwarp = blockIdx.x * 8 + w;        // 256 edges/block
    const int base  = gwarp * 32;

    const int s_own = src[base + L];     // coalesced
    const int d_own = dst[base + L];     // coalesced
    const float4* ea4 = (const float4*)edge_attr;

    // Phase A: partials
    #pragma unroll 2
    for (int i = 0; i < 32; i++) {
        const int e = base + i;
        const int s = __shfl_sync(0xFFFFFFFFu, s_own, i);

        float2 sf = *reinterpret_cast<const float2*>(&g_sf[s * DOUT + 2 * L]);
        ull f = packf2(sf.x, sf.y);

        #pragma unroll
        for (int g = 0; g < 4; g++) {
            float4 ev = __ldg(&ea4[e * 4 + g]);           // lane-uniform broadcast
            ffma2(f, wp[4 * g + 0], packf2(ev.x, ev.x));
            ffma2(f, wp[4 * g + 1], packf2(ev.y, ev.y));
            ffma2(f, wp[4 * g + 2], packf2(ev.z, ev.z));
            ffma2(f, wp[4 * g + 3], packf2(ev.w, ev.w));
        }

        float flo, fhi;
        unpackf2(f, flo, fhi);
        sP[w][i][L] = leaky(flo) * aL + leaky(fhi) * aH;
    }
    __syncwarp();

    // Phase B: lane L reduces its own edge (row L), conflict-free via pad 33
    float s0 = 0.f, s1 = 0.f, s2 = 0.f, s3 = 0.f;
    #pragma unroll
    for (int j = 0; j < 32; j += 4) {
        s0 += sP[w][L][j];
        s1 += sP[w][L][j + 1];
        s2 += sP[w][L][j + 2];
        s3 += sP[w][L][j + 3];
    }
    float logit = (s0 + s1) + (s2 + s3) + g_rdot[d_own];

    int pos = atomicAdd(&g_wptr[d_own], 1);               // spread-address
    g_ls[pos] = make_float2(logit, __int_as_float(s_own));
}

// ---------------- K5: warp-per-dst softmax + aggregation ----------------
__global__ __launch_bounds__(256) void k_aggregate(const float* __restrict__ bias,
                                                   float* __restrict__ out) {
    __shared__ float2 sA[8][32];          // [warp][idx] = {alpha, src-bits}

    const int lane = threadIdx.x & 31;
    const int w    = threadIdx.x >> 5;
    const int gw   = (blockIdx.x * blockDim.x + threadIdx.x) >> 5;
    if (gw >= NN) return;
    const int n = gw;

    int beg = g_rowptr[n];
    int end = g_rowptr[n + 1];
    int cnt = end - beg;

    float b0 = bias[2 * lane];
    float b1 = bias[2 * lane + 1];

    if (cnt == 0) {
        out[n * DOUT + 2 * lane]     = b0;
        out[n * DOUT + 2 * lane + 1] = b1;
        return;
    }

    float2 v = make_float2(-INFINITY, 0.0f);
    if (lane < cnt) v = g_ls[beg + lane];

    float lm = v.x;
    for (int j = beg + 32 + lane; j < end; j += 32)
        lm = fmaxf(lm, g_ls[j].x);
    float m = warp_max(lm);

    float le = (lane < cnt) ? __expf(v.x - m) : 0.0f;
    for (int j = beg + 32 + lane; j < end; j += 32)
        le += __expf(g_ls[j].x - m);
    float inv = 1.0f / warp_sum(le);

    sA[w][lane] = make_float2((lane < cnt) ? __expf(v.x - m) * inv : 0.0f, v.y);
    __syncwarp();

    float acc0 = 0.0f, acc1 = 0.0f;
    int lim = cnt < 32 ? cnt : 32;
    #pragma unroll 4
    for (int idx = 0; idx < lim; idx++) {
        float2 t = sA[w][idx];            // broadcast LDS.64
        int   s = __float_as_int(t.y);
        float a = t.x;
        float2 xv = *reinterpret_cast<const float2*>(&g_xt[s * DOUT + 2 * lane]);
        acc0 = fmaf(a, xv.x, acc0);
        acc1 = fmaf(a, xv.y, acc1);
    }
    for (int j = beg + 32; j < end; j++) {
        float2 lsv = g_ls[j];
        int   s = __float_as_int(lsv.y);
        float a = __expf(lsv.x - m) * inv;
        float2 xv = *reinterpret_cast<const float2*>(&g_xt[s * DOUT + 2 * lane]);
        acc0 = fmaf(a, xv.x, acc0);
        acc1 = fmaf(a, xv.y, acc1);
    }
    out[n * DOUT + 2 * lane]     = acc0 + b0;
    out[n * DOUT + 2 * lane + 1] = acc1 + b1;
}

// ---------------- launch ----------------
extern "C" void kernel_launch(void* const* d_in, const int* in_sizes, int n_in,
                              void* d_out, int out_size) {
    const float* x         = (const float*)d_in[0];
    const float* edge_attr = (const float*)d_in[1];
    const int*   src       = (const int*)d_in[2];
    const int*   dst       = (const int*)d_in[3];
    const float* W1        = (const float*)d_in[4];
    const float* W2        = (const float*)d_in[5];
    const float* attn      = (const float*)d_in[6];
    const float* bias      = (const float*)d_in[7];
    float* out             = (float*)d_out;

    void* count_ptr = nullptr;
    cudaGetSymbolAddress(&count_ptr, g_count);
    cudaMemsetAsync(count_ptr, 0, NN * sizeof(int));

    k_hist<<<(EE / 4 + 255) / 256, 256>>>(dst);
    k_node<<<NODE_BLOCKS, 256>>>(x, W1, W2, attn);
    k_scan1<<<SCAN_BLOCKS, SCAN_T>>>();
    k_scan23<<<(NN + 255) / 256, 256>>>();
    k_logits<<<EE / 256, 256>>>(edge_attr, src, dst, W1, attn);
    k_aggregate<<<(NN * 32 + 255) / 256, 256>>>(bias, out);
}